// round 7
// baseline (speedup 1.0000x reference)
#include <cuda_runtime.h>
#include <mma.h>
#include <cstdint>

using namespace nvcuda;

#define NQ    16384
#define KP    32
#define C     512
#define HREF  512
#define HCONF 256
#define NSTEPS 3

// ---------------- scratch (__device__ globals; no allocation allowed) ----------------
__device__ float g_wmean[NSTEPS * KP * C];
__device__ float g_wsum [NSTEPS * KP];
__device__ float g_h    [NSTEPS * KP * HREF];
__device__ float g_hp   [KP * HCONF];
__device__ float g_hq   [NQ * HCONF];        // 16 MB
__device__ float g_conf [KP];
__device__ unsigned g_bar;                   // grid barrier counter (persistent MLP)
__device__ unsigned g_cdone;                 // conf completion ticket

// ---------------- init ----------------
__global__ void init_kernel(const float* __restrict__ proto, float* __restrict__ out) {
    int idx = blockIdx.x * blockDim.x + threadIdx.x;
    if (idx < NSTEPS * KP * C)    g_wmean[idx] = 0.f;
    if (idx < NSTEPS * KP * HREF) g_h[idx]     = 0.f;
    if (idx < KP * HCONF)         g_hp[idx]    = 0.f;
    if (idx < NSTEPS * KP)        g_wsum[idx]  = 0.f;
    if (idx < KP)                 g_conf[idx]  = 0.f;
    if (idx == 0)                { g_bar = 0u; g_cdone = 0u; }
    if (idx < KP * C)             out[idx]     = proto[idx];
}

// ---------------- wmean via WMMA tf32: soft^T @ qf (R5 proven) ----------------
#define SOFT_LD 40
__global__ void __launch_bounds__(256) wmean_tc_kernel(const float* __restrict__ qd,
                                                       const float* __restrict__ qf) {
    extern __shared__ float sm[];
    float (*s_soft)[SOFT_LD] = (float(*)[SOFT_LD])sm;
    float (*s_out)[C]        = (float(*)[C])(sm + 256 * SOFT_LD);

    const int step  = blockIdx.y;
    const int qbase = blockIdx.x * 256;
    const int tid   = threadIdx.x;
    const int wid   = tid >> 5;

    {
        const float inv_t = 1.0f / (float)(step + 1);
        const float* row = qd + (size_t)(qbase + tid) * KP;
        float v[KP];
        float m = -1e30f;
#pragma unroll
        for (int i = 0; i < KP; i++) { v[i] = -row[i] * inv_t; m = fmaxf(m, v[i]); }
        float s = 0.f;
#pragma unroll
        for (int i = 0; i < KP; i++) { v[i] = __expf(v[i] - m); s += v[i]; }
        const float inv = 1.0f / s;
#pragma unroll
        for (int i = 0; i < KP; i++) s_soft[tid][i] = v[i] * inv;
    }
    __syncthreads();

    if (tid < KP) {
        float s = 0.f;
        for (int q = 0; q < 256; q++) s += s_soft[q][tid];
        atomicAdd(&g_wsum[step * KP + tid], s);
    }

    const int n0 = wid * 64;
    wmma::fragment<wmma::accumulator, 16, 16, 8, float> acc[2][4];
#pragma unroll
    for (int mi = 0; mi < 2; mi++)
#pragma unroll
        for (int ni = 0; ni < 4; ni++) wmma::fill_fragment(acc[mi][ni], 0.f);

    for (int kq = 0; kq < 256; kq += 8) {
        wmma::fragment<wmma::matrix_a, 16, 16, 8, wmma::precision::tf32, wmma::col_major> af[2];
        wmma::fragment<wmma::matrix_b, 16, 16, 8, wmma::precision::tf32, wmma::row_major> bf[4];
#pragma unroll
        for (int mi = 0; mi < 2; mi++) {
            wmma::load_matrix_sync(af[mi], &s_soft[kq][mi * 16], SOFT_LD);
#pragma unroll
            for (int t = 0; t < af[mi].num_elements; t++)
                af[mi].x[t] = wmma::__float_to_tf32(af[mi].x[t]);
        }
#pragma unroll
        for (int ni = 0; ni < 4; ni++) {
            wmma::load_matrix_sync(bf[ni], qf + (size_t)(qbase + kq) * C + n0 + ni * 16, C);
#pragma unroll
            for (int t = 0; t < bf[ni].num_elements; t++)
                bf[ni].x[t] = wmma::__float_to_tf32(bf[ni].x[t]);
        }
#pragma unroll
        for (int mi = 0; mi < 2; mi++)
#pragma unroll
            for (int ni = 0; ni < 4; ni++)
                wmma::mma_sync(acc[mi][ni], af[mi], bf[ni], acc[mi][ni]);
    }

#pragma unroll
    for (int mi = 0; mi < 2; mi++)
#pragma unroll
        for (int ni = 0; ni < 4; ni++)
            wmma::store_matrix_sync(&s_out[mi * 16][n0 + ni * 16], acc[mi][ni], C,
                                    wmma::mem_row_major);
    __syncthreads();

    float* base = g_wmean + (size_t)step * KP * C;
    const float* src = &s_out[0][0];
#pragma unroll
    for (int i = 0; i < 64; i++) {
        int idx = tid + 256 * i;
        atomicAdd(base + idx, src[idx]);
    }
}

// ---------------- persistent fused MLP: 3 steps of gemm1+gemm2 with grid barriers ----------------
// grid 128 (co-resident), block 256. Phase A map (8 n-tiles x 16 k-tiles), phase B (8 x 16).
__device__ __forceinline__ void grid_sync_at(unsigned want) {
    __threadfence();
    __syncthreads();
    if (threadIdx.x == 0) {
        atomicAdd(&g_bar, 1u);
        while (*(volatile unsigned*)&g_bar < want) __nanosleep(32);
    }
    __syncthreads();
}

__global__ void __launch_bounds__(256) mlp_fused_kernel(
        float* __restrict__ refined, const float* __restrict__ W1,
        const float* __restrict__ W2, const float* __restrict__ b1,
        const float* __restrict__ b2) {
    __shared__ float a_s[64][KP];        // 8 KB
    __shared__ float red[4][KP][64];     // 32 KB
    __shared__ float s_winv[NSTEPS][KP];

    const int tid = threadIdx.x;
    const int n  = tid & 63;
    const int kp = tid >> 6;
    const int bx = blockIdx.x & 7;
    const int by = blockIdx.x >> 3;

    if (tid < NSTEPS * KP)
        s_winv[tid >> 5][tid & 31] = 1.0f / fmaxf(g_wsum[tid], 1e-6f);

    unsigned want = gridDim.x;

    for (int step = 0; step < NSTEPS; step++) {
        // ======== phase A: g_h[step] += concat(refined, wmean[step]/wsum) @ W1 ========
        {
            const int ng = bx * 64 + n;
            const int kbase = by * 64;
            __syncthreads();   // s_winv ready (iter 0) / red reuse safe
#pragma unroll
            for (int r = 0; r < 8; r++) {
                int idx = tid + 256 * r;
                int ii = idx >> 5, k = idx & 31;
                int i = kbase + ii;
                a_s[ii][k] = (i < C)
                    ? __ldcg(&refined[k * C + i])
                    : g_wmean[(size_t)(step * KP + k) * C + (i - C)] * s_winv[step][k];
            }
            __syncthreads();

            float acc[KP];
#pragma unroll
            for (int k = 0; k < KP; k++) acc[k] = 0.f;

            const float* wptr = W1 + (size_t)(kbase + kp * 16) * HREF + ng;
            float wv[16];
#pragma unroll
            for (int ii = 0; ii < 16; ii++) wv[ii] = wptr[(size_t)ii * HREF];
#pragma unroll
            for (int ii = 0; ii < 16; ii++) {
                const float w = wv[ii];
                const float4* av = (const float4*)&a_s[kp * 16 + ii][0];
#pragma unroll
                for (int k4 = 0; k4 < 8; k4++) {
                    float4 a4 = av[k4];
                    acc[k4 * 4 + 0] = fmaf(a4.x, w, acc[k4 * 4 + 0]);
                    acc[k4 * 4 + 1] = fmaf(a4.y, w, acc[k4 * 4 + 1]);
                    acc[k4 * 4 + 2] = fmaf(a4.z, w, acc[k4 * 4 + 2]);
                    acc[k4 * 4 + 3] = fmaf(a4.w, w, acc[k4 * 4 + 3]);
                }
            }
#pragma unroll
            for (int k = 0; k < KP; k++) red[kp][k][n] = acc[k];
            __syncthreads();
            if (tid < 64) {
#pragma unroll
                for (int k = 0; k < KP; k++) {
                    float s = red[0][k][n] + red[1][k][n] + red[2][k][n] + red[3][k][n];
                    atomicAdd(&g_h[(size_t)(step * KP + k) * HREF + ng], s);
                }
            }
        }
        grid_sync_at(want); want += gridDim.x;

        // ======== phase B: refined += 0.1*(relu(g_h[step]+b1) @ W2 + b2) ========
        {
            const int cg = bx * 64 + n;
            const int jbase = by * 32;
#pragma unroll
            for (int r = 0; r < 4; r++) {
                int idx = tid + 256 * r;
                int ii = idx >> 5, k = idx & 31;
                int j = jbase + ii;
                a_s[ii][k] = fmaxf(__ldcg(&g_h[(size_t)(step * KP + k) * HREF + j]) + b1[j], 0.f);
            }
            __syncthreads();

            float acc[KP];
#pragma unroll
            for (int k = 0; k < KP; k++) acc[k] = 0.f;

            const float* wptr = W2 + (size_t)(jbase + kp * 8) * C + cg;
            float wv[8];
#pragma unroll
            for (int ii = 0; ii < 8; ii++) wv[ii] = wptr[(size_t)ii * C];
#pragma unroll
            for (int ii = 0; ii < 8; ii++) {
                const float w = wv[ii];
                const float4* av = (const float4*)&a_s[kp * 8 + ii][0];
#pragma unroll
                for (int k4 = 0; k4 < 8; k4++) {
                    float4 a4 = av[k4];
                    acc[k4 * 4 + 0] = fmaf(a4.x, w, acc[k4 * 4 + 0]);
                    acc[k4 * 4 + 1] = fmaf(a4.y, w, acc[k4 * 4 + 1]);
                    acc[k4 * 4 + 2] = fmaf(a4.z, w, acc[k4 * 4 + 2]);
                    acc[k4 * 4 + 3] = fmaf(a4.w, w, acc[k4 * 4 + 3]);
                }
            }
#pragma unroll
            for (int k = 0; k < KP; k++) red[kp][k][n] = acc[k];
            __syncthreads();
            if (tid < 64) {
                const float b2v = (by == 0) ? b2[cg] : 0.f;
#pragma unroll
                for (int k = 0; k < KP; k++) {
                    float s = red[0][k][n] + red[1][k][n] + red[2][k][n] + red[3][k][n];
                    atomicAdd(&refined[k * C + cg], 0.1f * (s + b2v));
                }
            }
        }
        if (step < NSTEPS - 1) { grid_sync_at(want); want += gridDim.x; }
    }
}

// ---------------- hp = prototypes @ Wc1[:C] (split-K, proven) ----------------
__global__ void hp_kernel(const float* __restrict__ proto, const float* __restrict__ Wc1) {
    __shared__ float a_s[32][KP];
    __shared__ float red[4][KP][64];
    const int tid = threadIdx.x;
    const int n  = tid & 63;
    const int kp = tid >> 6;
    const int ng = blockIdx.x * 64 + n;
    const int cbase = blockIdx.y * 32;

#pragma unroll
    for (int r = 0; r < 4; r++) {
        int idx = tid + 256 * r;
        int ii = idx >> 5, k = idx & 31;
        a_s[ii][k] = proto[k * C + cbase + ii];
    }
    __syncthreads();

    float acc[KP];
#pragma unroll
    for (int k = 0; k < KP; k++) acc[k] = 0.f;

    const float* wptr = Wc1 + (size_t)(cbase + kp * 8) * HCONF + ng;
    float wv[8];
#pragma unroll
    for (int ii = 0; ii < 8; ii++) wv[ii] = wptr[(size_t)ii * HCONF];
#pragma unroll
    for (int ii = 0; ii < 8; ii++) {
        const float w = wv[ii];
        const float4* av = (const float4*)&a_s[kp * 8 + ii][0];
#pragma unroll
        for (int k4 = 0; k4 < 8; k4++) {
            float4 a4 = av[k4];
            acc[k4 * 4 + 0] = fmaf(a4.x, w, acc[k4 * 4 + 0]);
            acc[k4 * 4 + 1] = fmaf(a4.y, w, acc[k4 * 4 + 1]);
            acc[k4 * 4 + 2] = fmaf(a4.z, w, acc[k4 * 4 + 2]);
            acc[k4 * 4 + 3] = fmaf(a4.w, w, acc[k4 * 4 + 3]);
        }
    }
#pragma unroll
    for (int k = 0; k < KP; k++) red[kp][k][n] = acc[k];
    __syncthreads();
    if (tid < 64) {
#pragma unroll
        for (int k = 0; k < KP; k++) {
            float s = red[0][k][n] + red[1][k][n] + red[2][k][n] + red[3][k][n];
            atomicAdd(&g_hp[k * HCONF + ng], s);
        }
    }
}

// ---------------- hq = qf @ Wq via WMMA tf32 (R5 proven) ----------------
#define A_LD 36
#define B_LD 68
__global__ void __launch_bounds__(256) hq_kernel(const float* __restrict__ qf,
                                                 const float* __restrict__ Wc1) {
    const float* __restrict__ B = Wc1 + (size_t)C * HCONF;
    __shared__ float As[128][A_LD];
    __shared__ float Bs[32][B_LD];

    const int tid = threadIdx.x;
    const int wid = tid >> 5;
    const int wm = wid >> 1;
    const int wn = wid & 1;
    const int m0 = blockIdx.x * 128;
    const int n0 = blockIdx.y * 64;

    wmma::fragment<wmma::accumulator, 16, 16, 8, float> acc[2][2];
#pragma unroll
    for (int mi = 0; mi < 2; mi++)
#pragma unroll
        for (int ni = 0; ni < 2; ni++) wmma::fill_fragment(acc[mi][ni], 0.f);

    for (int kk = 0; kk < C; kk += 32) {
        __syncthreads();
#pragma unroll
        for (int i = 0; i < 4; i++) {
            int f = tid + 256 * i; int row = f >> 3; int c4 = f & 7;
            *(float4*)&As[row][c4 * 4] = *(const float4*)(qf + (size_t)(m0 + row) * C + kk + c4 * 4);
        }
#pragma unroll
        for (int i = 0; i < 2; i++) {
            int f = tid + 256 * i; int row = f >> 4; int c4 = f & 15;
            *(float4*)&Bs[row][c4 * 4] = *(const float4*)(B + (size_t)(kk + row) * HCONF + n0 + c4 * 4);
        }
        __syncthreads();

#pragma unroll
        for (int s = 0; s < 4; s++) {
            wmma::fragment<wmma::matrix_a, 16, 16, 8, wmma::precision::tf32, wmma::row_major> af[2];
            wmma::fragment<wmma::matrix_b, 16, 16, 8, wmma::precision::tf32, wmma::row_major> bf[2];
#pragma unroll
            for (int mi = 0; mi < 2; mi++) {
                wmma::load_matrix_sync(af[mi], &As[wm * 32 + mi * 16][s * 8], A_LD);
#pragma unroll
                for (int t = 0; t < af[mi].num_elements; t++)
                    af[mi].x[t] = wmma::__float_to_tf32(af[mi].x[t]);
            }
#pragma unroll
            for (int ni = 0; ni < 2; ni++) {
                wmma::load_matrix_sync(bf[ni], &Bs[s * 8][wn * 32 + ni * 16], B_LD);
#pragma unroll
                for (int t = 0; t < bf[ni].num_elements; t++)
                    bf[ni].x[t] = wmma::__float_to_tf32(bf[ni].x[t]);
            }
#pragma unroll
            for (int mi = 0; mi < 2; mi++)
#pragma unroll
                for (int ni = 0; ni < 2; ni++)
                    wmma::mma_sync(acc[mi][ni], af[mi], bf[ni], acc[mi][ni]);
        }
    }

#pragma unroll
    for (int mi = 0; mi < 2; mi++)
#pragma unroll
        for (int ni = 0; ni < 2; ni++)
            wmma::store_matrix_sync(
                g_hq + (size_t)(m0 + wm * 32 + mi * 16) * HCONF + n0 + wn * 32 + ni * 16,
                acc[mi][ni], HCONF, wmma::mem_row_major);
}

// ---------------- conf + inline finalize (completion ticket) ----------------
__global__ void conf_kernel(const float* __restrict__ Wc2, const float* __restrict__ bc1,
                            const float* __restrict__ bc2, float* __restrict__ out) {
    __shared__ float s_hp[KP][HCONF];
    __shared__ float s_part[8][KP];
    __shared__ unsigned s_last;
    const int tid  = threadIdx.x;
    const int lane = tid & 31;
    const int warp = tid >> 5;

    float* hpflat = &s_hp[0][0];
#pragma unroll
    for (int r = 0; r < 32; r++) hpflat[tid + 256 * r] = g_hp[tid + 256 * r];

    float wc2r[8], bcr[8];
#pragma unroll
    for (int j = 0; j < 8; j++) {
        wc2r[j] = Wc2[lane + 32 * j];
        bcr[j]  = bc1[lane + 32 * j];
    }
    const float bc2v = bc2[0];
    __syncthreads();

    float conf_acc = 0.f;
    const int nwarps = gridDim.x * 8;
    for (int q = blockIdx.x * 8 + warp; q < NQ; q += nwarps) {
        float a[8];
#pragma unroll
        for (int j = 0; j < 8; j++) a[j] = g_hq[(size_t)q * HCONF + lane + 32 * j] + bcr[j];
#pragma unroll 4
        for (int k = 0; k < KP; k++) {
            float s = 0.f;
#pragma unroll
            for (int j = 0; j < 8; j++) {
                float t = fmaxf(s_hp[k][lane + 32 * j] + a[j], 0.f);
                s = fmaf(t, wc2r[j], s);
            }
            s += __shfl_xor_sync(0xffffffffu, s, 16);
            s += __shfl_xor_sync(0xffffffffu, s, 8);
            s += __shfl_xor_sync(0xffffffffu, s, 4);
            s += __shfl_xor_sync(0xffffffffu, s, 2);
            s += __shfl_xor_sync(0xffffffffu, s, 1);
            const float sig = 1.0f / (1.0f + __expf(-(s + bc2v)));
            if (k == lane) conf_acc += sig;
        }
    }
    s_part[warp][lane] = conf_acc;
    __syncthreads();
    if (tid < KP) {
        float t = 0.f;
#pragma unroll
        for (int w = 0; w < 8; w++) t += s_part[w][tid];
        atomicAdd(&g_conf[tid], t);
    }
    // completion ticket: last block finalizes the mean
    __threadfence();
    __syncthreads();
    if (tid == 0) s_last = atomicAdd(&g_cdone, 1u);
    __syncthreads();
    if (s_last == gridDim.x - 1) {
        if (tid < KP)
            out[KP * C + tid] = *((volatile float*)&g_conf[tid]) * (1.0f / (float)NQ);
    }
}

// ---------------- launch ----------------
extern "C" void kernel_launch(void* const* d_in, const int* in_sizes, int n_in,
                              void* d_out, int out_size) {
    const float* proto = (const float*)d_in[0];
    const float* qf    = (const float*)d_in[1];
    const float* qd    = (const float*)d_in[2];
    const float* W1    = (const float*)d_in[3];
    const float* b1    = (const float*)d_in[4];
    const float* W2    = (const float*)d_in[5];
    const float* b2    = (const float*)d_in[6];
    const float* Wc1   = (const float*)d_in[7];
    const float* bc1   = (const float*)d_in[8];
    const float* Wc2   = (const float*)d_in[9];
    const float* bc2   = (const float*)d_in[10];
    float* out = (float*)d_out;

    const int WM_SMEM = 256 * SOFT_LD * 4 + KP * C * 4;   // 106496
    static int smem_set = 0;
    if (!smem_set) {
        cudaFuncSetAttribute(wmean_tc_kernel, cudaFuncAttributeMaxDynamicSharedMemorySize, WM_SMEM);
        smem_set = 1;
    }

    init_kernel<<<192, 256>>>(proto, out);
    wmean_tc_kernel<<<dim3(NQ / 256, NSTEPS), 256, WM_SMEM>>>(qd, qf);
    mlp_fused_kernel<<<128, 256>>>(out, W1, W2, b1, b2);
    hp_kernel<<<dim3(HCONF / 64, C / 32), 256>>>(proto, Wc1);
    hq_kernel<<<dim3(NQ / 128, HCONF / 64), 256>>>(qf, Wc1);
    conf_kernel<<<256, 256>>>(Wc2, bc1, bc2, out);
}

// round 8
// speedup vs baseline: 1.3512x; 1.3512x over previous
#include <cuda_runtime.h>
#include <cuda_bf16.h>
#include <mma.h>
#include <cstdint>

using namespace nvcuda;

#define NQ    16384
#define KP    32
#define C     512
#define HREF  512
#define HCONF 256
#define NSTEPS 3

// ---------------- scratch (__device__ globals; no allocation allowed) ----------------
__device__ float g_wmean[NSTEPS * KP * C];
__device__ float g_wsum [NSTEPS * KP];
__device__ float g_h    [NSTEPS * KP * HREF];
__device__ float g_hp   [KP * HCONF];
__device__ float g_hq   [NQ * HCONF];                 // 16 MB
__device__ float g_conf [KP];
__device__ __nv_bfloat16 g_qf16[NQ * C];              // 16 MB
__device__ __nv_bfloat16 g_wq16[C * HCONF];           // 256 KB
__device__ unsigned g_bar;
__device__ unsigned g_cdone;

// ---------------- init ----------------
__global__ void init_kernel(const float* __restrict__ proto, float* __restrict__ out) {
    int idx = blockIdx.x * blockDim.x + threadIdx.x;
    if (idx < NSTEPS * KP * C)    g_wmean[idx] = 0.f;
    if (idx < NSTEPS * KP * HREF) g_h[idx]     = 0.f;
    if (idx < KP * HCONF)         g_hp[idx]    = 0.f;
    if (idx < NSTEPS * KP)        g_wsum[idx]  = 0.f;
    if (idx < KP)                 g_conf[idx]  = 0.f;
    if (idx == 0)                { g_bar = 0u; g_cdone = 0u; }
    if (idx < KP * C)             out[idx]     = proto[idx];
}

// ---------------- one-time f32 -> bf16 conversion of qf and Wq ----------------
// vec = 8 elements. qf: 1048576 vecs, Wq: 16384 vecs. grid 4160 x 256.
__global__ void cvt_kernel(const float* __restrict__ qf, const float* __restrict__ Wc1) {
    const int idx = blockIdx.x * blockDim.x + threadIdx.x;
    const int NV_QF = NQ * C / 8;
    const float* src;
    __nv_bfloat16* dst;
    int v;
    if (idx < NV_QF) { src = qf; dst = g_qf16; v = idx; }
    else if (idx < NV_QF + C * HCONF / 8) {
        src = Wc1 + (size_t)C * HCONF; dst = g_wq16; v = idx - NV_QF;
    } else return;
    float4 a = *(const float4*)(src + (size_t)v * 8);
    float4 b = *(const float4*)(src + (size_t)v * 8 + 4);
    __nv_bfloat162 p0 = __floats2bfloat162_rn(a.x, a.y);
    __nv_bfloat162 p1 = __floats2bfloat162_rn(a.z, a.w);
    __nv_bfloat162 p2 = __floats2bfloat162_rn(b.x, b.y);
    __nv_bfloat162 p3 = __floats2bfloat162_rn(b.z, b.w);
    uint4 o;
    o.x = *(uint32_t*)&p0; o.y = *(uint32_t*)&p1;
    o.z = *(uint32_t*)&p2; o.w = *(uint32_t*)&p3;
    *(uint4*)(dst + (size_t)v * 8) = o;
}

// ---------------- wmean via WMMA bf16: soft^T @ qf ----------------
// grid (NQ/256, 3), block 256 (8 warps). dyn smem: s_soft bf16[256][40] (20480 B)
// + s_out f32[32][512] (65536 B) = 86016 B
#define SOFT_LD 40
__global__ void __launch_bounds__(256) wmean_tc_kernel(const float* __restrict__ qd) {
    extern __shared__ char smraw[];
    __nv_bfloat16 (*s_soft)[SOFT_LD] = (__nv_bfloat16(*)[SOFT_LD])smraw;
    float (*s_out)[C] = (float(*)[C])(smraw + 256 * SOFT_LD * 2);

    const int step  = blockIdx.y;
    const int qbase = blockIdx.x * 256;
    const int tid   = threadIdx.x;
    const int wid   = tid >> 5;

    {
        const float inv_t = 1.0f / (float)(step + 1);
        const float* row = qd + (size_t)(qbase + tid) * KP;
        float v[KP];
        float m = -1e30f;
#pragma unroll
        for (int i = 0; i < KP; i++) { v[i] = -row[i] * inv_t; m = fmaxf(m, v[i]); }
        float s = 0.f;
#pragma unroll
        for (int i = 0; i < KP; i++) { v[i] = __expf(v[i] - m); s += v[i]; }
        const float inv = 1.0f / s;
#pragma unroll
        for (int i = 0; i < KP; i++) s_soft[tid][i] = __float2bfloat16(v[i] * inv);
    }
    __syncthreads();

    if (tid < KP) {   // wsum from the bf16-rounded weights (consistent with numerator)
        float s = 0.f;
        for (int q = 0; q < 256; q++) s += __bfloat162float(s_soft[q][tid]);
        atomicAdd(&g_wsum[step * KP + tid], s);
    }

    const int n0 = wid * 64;
    wmma::fragment<wmma::accumulator, 16, 16, 16, float> acc[2][4];
#pragma unroll
    for (int mi = 0; mi < 2; mi++)
#pragma unroll
        for (int ni = 0; ni < 4; ni++) wmma::fill_fragment(acc[mi][ni], 0.f);

    for (int kq = 0; kq < 256; kq += 16) {
        wmma::fragment<wmma::matrix_a, 16, 16, 16, __nv_bfloat16, wmma::col_major> af[2];
        wmma::fragment<wmma::matrix_b, 16, 16, 16, __nv_bfloat16, wmma::row_major> bf[4];
#pragma unroll
        for (int mi = 0; mi < 2; mi++)
            wmma::load_matrix_sync(af[mi], &s_soft[kq][mi * 16], SOFT_LD);
#pragma unroll
        for (int ni = 0; ni < 4; ni++)
            wmma::load_matrix_sync(bf[ni], g_qf16 + (size_t)(qbase + kq) * C + n0 + ni * 16, C);
#pragma unroll
        for (int mi = 0; mi < 2; mi++)
#pragma unroll
            for (int ni = 0; ni < 4; ni++)
                wmma::mma_sync(acc[mi][ni], af[mi], bf[ni], acc[mi][ni]);
    }

#pragma unroll
    for (int mi = 0; mi < 2; mi++)
#pragma unroll
        for (int ni = 0; ni < 4; ni++)
            wmma::store_matrix_sync(&s_out[mi * 16][n0 + ni * 16], acc[mi][ni], C,
                                    wmma::mem_row_major);
    __syncthreads();

    float* base = g_wmean + (size_t)step * KP * C;
    const float* src = &s_out[0][0];
#pragma unroll
    for (int i = 0; i < 64; i++) {
        int idx = tid + 256 * i;
        atomicAdd(base + idx, src[idx]);
    }
}

// ---------------- persistent fused MLP (R7 proven) ----------------
__device__ __forceinline__ void grid_sync_at(unsigned want) {
    __threadfence();
    __syncthreads();
    if (threadIdx.x == 0) {
        atomicAdd(&g_bar, 1u);
        while (*(volatile unsigned*)&g_bar < want) __nanosleep(32);
    }
    __syncthreads();
}

__global__ void __launch_bounds__(256) mlp_fused_kernel(
        float* __restrict__ refined, const float* __restrict__ W1,
        const float* __restrict__ W2, const float* __restrict__ b1,
        const float* __restrict__ b2) {
    __shared__ float a_s[64][KP];
    __shared__ float red[4][KP][64];
    __shared__ float s_winv[NSTEPS][KP];

    const int tid = threadIdx.x;
    const int n  = tid & 63;
    const int kp = tid >> 6;
    const int bx = blockIdx.x & 7;
    const int by = blockIdx.x >> 3;

    if (tid < NSTEPS * KP)
        s_winv[tid >> 5][tid & 31] = 1.0f / fmaxf(g_wsum[tid], 1e-6f);

    unsigned want = gridDim.x;

    for (int step = 0; step < NSTEPS; step++) {
        {
            const int ng = bx * 64 + n;
            const int kbase = by * 64;
            __syncthreads();
#pragma unroll
            for (int r = 0; r < 8; r++) {
                int idx = tid + 256 * r;
                int ii = idx >> 5, k = idx & 31;
                int i = kbase + ii;
                a_s[ii][k] = (i < C)
                    ? __ldcg(&refined[k * C + i])
                    : g_wmean[(size_t)(step * KP + k) * C + (i - C)] * s_winv[step][k];
            }
            __syncthreads();

            float acc[KP];
#pragma unroll
            for (int k = 0; k < KP; k++) acc[k] = 0.f;

            const float* wptr = W1 + (size_t)(kbase + kp * 16) * HREF + ng;
            float wv[16];
#pragma unroll
            for (int ii = 0; ii < 16; ii++) wv[ii] = wptr[(size_t)ii * HREF];
#pragma unroll
            for (int ii = 0; ii < 16; ii++) {
                const float w = wv[ii];
                const float4* av = (const float4*)&a_s[kp * 16 + ii][0];
#pragma unroll
                for (int k4 = 0; k4 < 8; k4++) {
                    float4 a4 = av[k4];
                    acc[k4 * 4 + 0] = fmaf(a4.x, w, acc[k4 * 4 + 0]);
                    acc[k4 * 4 + 1] = fmaf(a4.y, w, acc[k4 * 4 + 1]);
                    acc[k4 * 4 + 2] = fmaf(a4.z, w, acc[k4 * 4 + 2]);
                    acc[k4 * 4 + 3] = fmaf(a4.w, w, acc[k4 * 4 + 3]);
                }
            }
#pragma unroll
            for (int k = 0; k < KP; k++) red[kp][k][n] = acc[k];
            __syncthreads();
            if (tid < 64) {
#pragma unroll
                for (int k = 0; k < KP; k++) {
                    float s = red[0][k][n] + red[1][k][n] + red[2][k][n] + red[3][k][n];
                    atomicAdd(&g_h[(size_t)(step * KP + k) * HREF + ng], s);
                }
            }
        }
        grid_sync_at(want); want += gridDim.x;

        {
            const int cg = bx * 64 + n;
            const int jbase = by * 32;
#pragma unroll
            for (int r = 0; r < 4; r++) {
                int idx = tid + 256 * r;
                int ii = idx >> 5, k = idx & 31;
                int j = jbase + ii;
                a_s[ii][k] = fmaxf(__ldcg(&g_h[(size_t)(step * KP + k) * HREF + j]) + b1[j], 0.f);
            }
            __syncthreads();

            float acc[KP];
#pragma unroll
            for (int k = 0; k < KP; k++) acc[k] = 0.f;

            const float* wptr = W2 + (size_t)(jbase + kp * 8) * C + cg;
            float wv[8];
#pragma unroll
            for (int ii = 0; ii < 8; ii++) wv[ii] = wptr[(size_t)ii * C];
#pragma unroll
            for (int ii = 0; ii < 8; ii++) {
                const float w = wv[ii];
                const float4* av = (const float4*)&a_s[kp * 8 + ii][0];
#pragma unroll
                for (int k4 = 0; k4 < 8; k4++) {
                    float4 a4 = av[k4];
                    acc[k4 * 4 + 0] = fmaf(a4.x, w, acc[k4 * 4 + 0]);
                    acc[k4 * 4 + 1] = fmaf(a4.y, w, acc[k4 * 4 + 1]);
                    acc[k4 * 4 + 2] = fmaf(a4.z, w, acc[k4 * 4 + 2]);
                    acc[k4 * 4 + 3] = fmaf(a4.w, w, acc[k4 * 4 + 3]);
                }
            }
#pragma unroll
            for (int k = 0; k < KP; k++) red[kp][k][n] = acc[k];
            __syncthreads();
            if (tid < 64) {
                const float b2v = (by == 0) ? b2[cg] : 0.f;
#pragma unroll
                for (int k = 0; k < KP; k++) {
                    float s = red[0][k][n] + red[1][k][n] + red[2][k][n] + red[3][k][n];
                    atomicAdd(&refined[k * C + cg], 0.1f * (s + b2v));
                }
            }
        }
        if (step < NSTEPS - 1) { grid_sync_at(want); want += gridDim.x; }
    }
}

// ---------------- hp = prototypes @ Wc1[:C] (split-K, proven) ----------------
__global__ void hp_kernel(const float* __restrict__ proto, const float* __restrict__ Wc1) {
    __shared__ float a_s[32][KP];
    __shared__ float red[4][KP][64];
    const int tid = threadIdx.x;
    const int n  = tid & 63;
    const int kp = tid >> 6;
    const int ng = blockIdx.x * 64 + n;
    const int cbase = blockIdx.y * 32;

#pragma unroll
    for (int r = 0; r < 4; r++) {
        int idx = tid + 256 * r;
        int ii = idx >> 5, k = idx & 31;
        a_s[ii][k] = proto[k * C + cbase + ii];
    }
    __syncthreads();

    float acc[KP];
#pragma unroll
    for (int k = 0; k < KP; k++) acc[k] = 0.f;

    const float* wptr = Wc1 + (size_t)(cbase + kp * 8) * HCONF + ng;
    float wv[8];
#pragma unroll
    for (int ii = 0; ii < 8; ii++) wv[ii] = wptr[(size_t)ii * HCONF];
#pragma unroll
    for (int ii = 0; ii < 8; ii++) {
        const float w = wv[ii];
        const float4* av = (const float4*)&a_s[kp * 8 + ii][0];
#pragma unroll
        for (int k4 = 0; k4 < 8; k4++) {
            float4 a4 = av[k4];
            acc[k4 * 4 + 0] = fmaf(a4.x, w, acc[k4 * 4 + 0]);
            acc[k4 * 4 + 1] = fmaf(a4.y, w, acc[k4 * 4 + 1]);
            acc[k4 * 4 + 2] = fmaf(a4.z, w, acc[k4 * 4 + 2]);
            acc[k4 * 4 + 3] = fmaf(a4.w, w, acc[k4 * 4 + 3]);
        }
    }
#pragma unroll
    for (int k = 0; k < KP; k++) red[kp][k][n] = acc[k];
    __syncthreads();
    if (tid < 64) {
#pragma unroll
        for (int k = 0; k < KP; k++) {
            float s = red[0][k][n] + red[1][k][n] + red[2][k][n] + red[3][k][n];
            atomicAdd(&g_hp[k * HCONF + ng], s);
        }
    }
}

// ---------------- hq = qf @ Wq via WMMA bf16 (16x16x16, K-chunk 64) ----------------
#define HA_LD 72
#define HB_LD 72
__global__ void __launch_bounds__(256) hq_kernel() {
    __shared__ __nv_bfloat16 As[128][HA_LD];   // 18432 B
    __shared__ __nv_bfloat16 Bs[64][HB_LD];    //  9216 B

    const int tid = threadIdx.x;
    const int wid = tid >> 5;
    const int wm = wid >> 1;
    const int wn = wid & 1;
    const int m0 = blockIdx.x * 128;
    const int n0 = blockIdx.y * 64;

    wmma::fragment<wmma::accumulator, 16, 16, 16, float> acc[2][2];
#pragma unroll
    for (int mi = 0; mi < 2; mi++)
#pragma unroll
        for (int ni = 0; ni < 2; ni++) wmma::fill_fragment(acc[mi][ni], 0.f);

    for (int kk = 0; kk < C; kk += 64) {
        __syncthreads();
        // A tile 128x64 bf16: 1024 uint4, 4/thread
#pragma unroll
        for (int i = 0; i < 4; i++) {
            int f = tid + 256 * i; int row = f >> 3; int c8 = f & 7;
            *(uint4*)&As[row][c8 * 8] =
                *(const uint4*)(g_qf16 + (size_t)(m0 + row) * C + kk + c8 * 8);
        }
        // B tile 64x64 bf16: 512 uint4, 2/thread
#pragma unroll
        for (int i = 0; i < 2; i++) {
            int f = tid + 256 * i; int row = f >> 3; int c8 = f & 7;
            *(uint4*)&Bs[row][c8 * 8] =
                *(const uint4*)(g_wq16 + (size_t)(kk + row) * HCONF + n0 + c8 * 8);
        }
        __syncthreads();

#pragma unroll
        for (int s = 0; s < 4; s++) {
            wmma::fragment<wmma::matrix_a, 16, 16, 16, __nv_bfloat16, wmma::row_major> af[2];
            wmma::fragment<wmma::matrix_b, 16, 16, 16, __nv_bfloat16, wmma::row_major> bf[2];
#pragma unroll
            for (int mi = 0; mi < 2; mi++)
                wmma::load_matrix_sync(af[mi], &As[wm * 32 + mi * 16][s * 16], HA_LD);
#pragma unroll
            for (int ni = 0; ni < 2; ni++)
                wmma::load_matrix_sync(bf[ni], &Bs[s * 16][wn * 32 + ni * 16], HB_LD);
#pragma unroll
            for (int mi = 0; mi < 2; mi++)
#pragma unroll
                for (int ni = 0; ni < 2; ni++)
                    wmma::mma_sync(acc[mi][ni], af[mi], bf[ni], acc[mi][ni]);
        }
    }

#pragma unroll
    for (int mi = 0; mi < 2; mi++)
#pragma unroll
        for (int ni = 0; ni < 2; ni++)
            wmma::store_matrix_sync(
                g_hq + (size_t)(m0 + wm * 32 + mi * 16) * HCONF + n0 + wn * 32 + ni * 16,
                acc[mi][ni], HCONF, wmma::mem_row_major);
}

// ---------------- conf + inline finalize (R7 proven) ----------------
__global__ void conf_kernel(const float* __restrict__ Wc2, const float* __restrict__ bc1,
                            const float* __restrict__ bc2, float* __restrict__ out) {
    __shared__ float s_hp[KP][HCONF];
    __shared__ float s_part[8][KP];
    __shared__ unsigned s_last;
    const int tid  = threadIdx.x;
    const int lane = tid & 31;
    const int warp = tid >> 5;

    float* hpflat = &s_hp[0][0];
#pragma unroll
    for (int r = 0; r < 32; r++) hpflat[tid + 256 * r] = g_hp[tid + 256 * r];

    float wc2r[8], bcr[8];
#pragma unroll
    for (int j = 0; j < 8; j++) {
        wc2r[j] = Wc2[lane + 32 * j];
        bcr[j]  = bc1[lane + 32 * j];
    }
    const float bc2v = bc2[0];
    __syncthreads();

    float conf_acc = 0.f;
    const int nwarps = gridDim.x * 8;
    for (int q = blockIdx.x * 8 + warp; q < NQ; q += nwarps) {
        float a[8];
#pragma unroll
        for (int j = 0; j < 8; j++) a[j] = g_hq[(size_t)q * HCONF + lane + 32 * j] + bcr[j];
#pragma unroll 4
        for (int k = 0; k < KP; k++) {
            float s = 0.f;
#pragma unroll
            for (int j = 0; j < 8; j++) {
                float t = fmaxf(s_hp[k][lane + 32 * j] + a[j], 0.f);
                s = fmaf(t, wc2r[j], s);
            }
            s += __shfl_xor_sync(0xffffffffu, s, 16);
            s += __shfl_xor_sync(0xffffffffu, s, 8);
            s += __shfl_xor_sync(0xffffffffu, s, 4);
            s += __shfl_xor_sync(0xffffffffu, s, 2);
            s += __shfl_xor_sync(0xffffffffu, s, 1);
            const float sig = 1.0f / (1.0f + __expf(-(s + bc2v)));
            if (k == lane) conf_acc += sig;
        }
    }
    s_part[warp][lane] = conf_acc;
    __syncthreads();
    if (tid < KP) {
        float t = 0.f;
#pragma unroll
        for (int w = 0; w < 8; w++) t += s_part[w][tid];
        atomicAdd(&g_conf[tid], t);
    }
    __threadfence();
    __syncthreads();
    if (tid == 0) s_last = atomicAdd(&g_cdone, 1u);
    __syncthreads();
    if (s_last == gridDim.x - 1) {
        if (tid < KP)
            out[KP * C + tid] = *((volatile float*)&g_conf[tid]) * (1.0f / (float)NQ);
    }
}

// ---------------- launch ----------------
extern "C" void kernel_launch(void* const* d_in, const int* in_sizes, int n_in,
                              void* d_out, int out_size) {
    const float* proto = (const float*)d_in[0];
    const float* qf    = (const float*)d_in[1];
    const float* qd    = (const float*)d_in[2];
    const float* W1    = (const float*)d_in[3];
    const float* b1    = (const float*)d_in[4];
    const float* W2    = (const float*)d_in[5];
    const float* b2    = (const float*)d_in[6];
    const float* Wc1   = (const float*)d_in[7];
    const float* bc1   = (const float*)d_in[8];
    const float* Wc2   = (const float*)d_in[9];
    const float* bc2   = (const float*)d_in[10];
    float* out = (float*)d_out;

    const int WM_SMEM = 256 * SOFT_LD * 2 + KP * C * 4;   // 20480 + 65536 = 86016
    static int smem_set = 0;
    if (!smem_set) {
        cudaFuncSetAttribute(wmean_tc_kernel, cudaFuncAttributeMaxDynamicSharedMemorySize, WM_SMEM);
        smem_set = 1;
    }

    init_kernel<<<192, 256>>>(proto, out);
    cvt_kernel<<<4160, 256>>>(qf, Wc1);
    wmean_tc_kernel<<<dim3(NQ / 256, NSTEPS), 256, WM_SMEM>>>(qd);
    mlp_fused_kernel<<<128, 256>>>(out, W1, W2, b1, b2);
    hp_kernel<<<dim3(HCONF / 64, C / 32), 256>>>(proto, Wc1);
    hq_kernel<<<dim3(NQ / 128, HCONF / 64), 256>>>();
    conf_kernel<<<256, 256>>>(Wc2, bc1, bc2, out);
}

// round 9
// speedup vs baseline: 1.4050x; 1.0399x over previous
#include <cuda_runtime.h>
#include <cuda_bf16.h>
#include <mma.h>
#include <cstdint>

using namespace nvcuda;

#define NQ    16384
#define KP    32
#define C     512
#define HREF  512
#define HCONF 256
#define NSTEPS 3

#define MLPB  128      // mlp role blocks (grid-barrier cohort)
#define CONFB 160      // conf role blocks

// ---------------- scratch ----------------
__device__ float g_wmean[NSTEPS * KP * C];
__device__ float g_wsum [NSTEPS * KP];
__device__ float g_h    [NSTEPS * KP * HREF];
__device__ float g_hp   [KP * HCONF];
__device__ float g_hq   [NQ * HCONF];                 // 16 MB
__device__ float g_conf [KP];
__device__ __nv_bfloat16 g_qf16[NQ * C];              // 16 MB
__device__ __nv_bfloat16 g_wq16[C * HCONF];           // 256 KB
__device__ unsigned g_bar;
__device__ unsigned g_cdone;

// ================= K0: cvt (blocks 0..4159) + init (blocks 4160..4351) =================
__global__ void __launch_bounds__(256) k0_kernel(const float* __restrict__ proto,
                                                 const float* __restrict__ qf,
                                                 const float* __restrict__ Wc1,
                                                 float* __restrict__ out) {
    const int bid = blockIdx.x;
    if (bid < 4160) {
        const int idx = bid * 256 + threadIdx.x;
        const int NV_QF = NQ * C / 8;
        const float* src;
        __nv_bfloat16* dst;
        int v;
        if (idx < NV_QF) { src = qf; dst = g_qf16; v = idx; }
        else if (idx < NV_QF + C * HCONF / 8) {
            src = Wc1 + (size_t)C * HCONF; dst = g_wq16; v = idx - NV_QF;
        } else return;
        float4 a = *(const float4*)(src + (size_t)v * 8);
        float4 b = *(const float4*)(src + (size_t)v * 8 + 4);
        __nv_bfloat162 p0 = __floats2bfloat162_rn(a.x, a.y);
        __nv_bfloat162 p1 = __floats2bfloat162_rn(a.z, a.w);
        __nv_bfloat162 p2 = __floats2bfloat162_rn(b.x, b.y);
        __nv_bfloat162 p3 = __floats2bfloat162_rn(b.z, b.w);
        uint4 o;
        o.x = *(uint32_t*)&p0; o.y = *(uint32_t*)&p1;
        o.z = *(uint32_t*)&p2; o.w = *(uint32_t*)&p3;
        *(uint4*)(dst + (size_t)v * 8) = o;
    } else {
        const int idx = (bid - 4160) * 256 + threadIdx.x;
        if (idx < NSTEPS * KP * C)    g_wmean[idx] = 0.f;
        if (idx < NSTEPS * KP * HREF) g_h[idx]     = 0.f;
        if (idx < KP * HCONF)         g_hp[idx]    = 0.f;
        if (idx < NSTEPS * KP)        g_wsum[idx]  = 0.f;
        if (idx < KP)                 g_conf[idx]  = 0.f;
        if (idx == 0)                { g_bar = 0u; g_cdone = 0u; }
        if (idx < KP * C)             out[idx]     = proto[idx];
    }
}

// ================= K1: wmean (0..191) + hq (192..447, 2 tiles) + hp (448..511) =========
#define SOFT_LD 40
#define HA_LD 72
#define HB_LD 72
#define K1_SMEM 86016

__device__ __forceinline__ void wmean_role(const float* __restrict__ qd, char* smraw,
                                           int step, int qbase) {
    __nv_bfloat16 (*s_soft)[SOFT_LD] = (__nv_bfloat16(*)[SOFT_LD])smraw;
    float (*s_out)[C] = (float(*)[C])(smraw + 256 * SOFT_LD * 2);
    const int tid = threadIdx.x;
    const int wid = tid >> 5;

    {
        const float inv_t = 1.0f / (float)(step + 1);
        const float* row = qd + (size_t)(qbase + tid) * KP;
        float v[KP];
        float m = -1e30f;
#pragma unroll
        for (int i = 0; i < KP; i++) { v[i] = -row[i] * inv_t; m = fmaxf(m, v[i]); }
        float s = 0.f;
#pragma unroll
        for (int i = 0; i < KP; i++) { v[i] = __expf(v[i] - m); s += v[i]; }
        const float inv = 1.0f / s;
#pragma unroll
        for (int i = 0; i < KP; i++) s_soft[tid][i] = __float2bfloat16(v[i] * inv);
    }
    __syncthreads();

    if (tid < KP) {
        float s = 0.f;
        for (int q = 0; q < 256; q++) s += __bfloat162float(s_soft[q][tid]);
        atomicAdd(&g_wsum[step * KP + tid], s);
    }

    const int n0 = wid * 64;
    wmma::fragment<wmma::accumulator, 16, 16, 16, float> acc[2][4];
#pragma unroll
    for (int mi = 0; mi < 2; mi++)
#pragma unroll
        for (int ni = 0; ni < 4; ni++) wmma::fill_fragment(acc[mi][ni], 0.f);

    for (int kq = 0; kq < 256; kq += 16) {
        wmma::fragment<wmma::matrix_a, 16, 16, 16, __nv_bfloat16, wmma::col_major> af[2];
        wmma::fragment<wmma::matrix_b, 16, 16, 16, __nv_bfloat16, wmma::row_major> bf[4];
#pragma unroll
        for (int mi = 0; mi < 2; mi++)
            wmma::load_matrix_sync(af[mi], &s_soft[kq][mi * 16], SOFT_LD);
#pragma unroll
        for (int ni = 0; ni < 4; ni++)
            wmma::load_matrix_sync(bf[ni], g_qf16 + (size_t)(qbase + kq) * C + n0 + ni * 16, C);
#pragma unroll
        for (int mi = 0; mi < 2; mi++)
#pragma unroll
            for (int ni = 0; ni < 4; ni++)
                wmma::mma_sync(acc[mi][ni], af[mi], bf[ni], acc[mi][ni]);
    }

#pragma unroll
    for (int mi = 0; mi < 2; mi++)
#pragma unroll
        for (int ni = 0; ni < 4; ni++)
            wmma::store_matrix_sync(&s_out[mi * 16][n0 + ni * 16], acc[mi][ni], C,
                                    wmma::mem_row_major);
    __syncthreads();

    float* base = g_wmean + (size_t)step * KP * C;
    const float* src = &s_out[0][0];
#pragma unroll
    for (int i = 0; i < 64; i++) {
        int idx = tid + 256 * i;
        atomicAdd(base + idx, src[idx]);
    }
}

__device__ __forceinline__ void hq_role(char* smraw, int t0) {
    __nv_bfloat16 (*As)[HA_LD] = (__nv_bfloat16(*)[HA_LD])smraw;
    __nv_bfloat16 (*Bs)[HB_LD] = (__nv_bfloat16(*)[HB_LD])(smraw + 128 * HA_LD * 2);
    const int tid = threadIdx.x;
    const int wid = tid >> 5;
    const int wm = wid >> 1;
    const int wn = wid & 1;

    for (int t = t0; t < t0 + 2; t++) {
        const int m0 = (t & 127) * 128;
        const int n0 = (t >> 7) * 64;

        wmma::fragment<wmma::accumulator, 16, 16, 16, float> acc[2][2];
#pragma unroll
        for (int mi = 0; mi < 2; mi++)
#pragma unroll
            for (int ni = 0; ni < 2; ni++) wmma::fill_fragment(acc[mi][ni], 0.f);

        for (int kk = 0; kk < C; kk += 64) {
            __syncthreads();
#pragma unroll
            for (int i = 0; i < 4; i++) {
                int f = tid + 256 * i; int row = f >> 3; int c8 = f & 7;
                *(uint4*)&As[row][c8 * 8] =
                    *(const uint4*)(g_qf16 + (size_t)(m0 + row) * C + kk + c8 * 8);
            }
#pragma unroll
            for (int i = 0; i < 2; i++) {
                int f = tid + 256 * i; int row = f >> 3; int c8 = f & 7;
                *(uint4*)&Bs[row][c8 * 8] =
                    *(const uint4*)(g_wq16 + (size_t)(kk + row) * HCONF + n0 + c8 * 8);
            }
            __syncthreads();

#pragma unroll
            for (int s = 0; s < 4; s++) {
                wmma::fragment<wmma::matrix_a, 16, 16, 16, __nv_bfloat16, wmma::row_major> af[2];
                wmma::fragment<wmma::matrix_b, 16, 16, 16, __nv_bfloat16, wmma::row_major> bf[2];
#pragma unroll
                for (int mi = 0; mi < 2; mi++)
                    wmma::load_matrix_sync(af[mi], &As[wm * 32 + mi * 16][s * 16], HA_LD);
#pragma unroll
                for (int ni = 0; ni < 2; ni++)
                    wmma::load_matrix_sync(bf[ni], &Bs[s * 16][wn * 32 + ni * 16], HB_LD);
#pragma unroll
                for (int mi = 0; mi < 2; mi++)
#pragma unroll
                    for (int ni = 0; ni < 2; ni++)
                        wmma::mma_sync(acc[mi][ni], af[mi], bf[ni], acc[mi][ni]);
            }
        }
#pragma unroll
        for (int mi = 0; mi < 2; mi++)
#pragma unroll
            for (int ni = 0; ni < 2; ni++)
                wmma::store_matrix_sync(
                    g_hq + (size_t)(m0 + wm * 32 + mi * 16) * HCONF + n0 + wn * 32 + ni * 16,
                    acc[mi][ni], HCONF, wmma::mem_row_major);
    }
}

__device__ __forceinline__ void hp_role(const float* __restrict__ proto,
                                        const float* __restrict__ Wc1, char* smraw, int b) {
    float (*a_s)[KP] = (float(*)[KP])smraw;                       // [32][32]
    float (*red)[KP][64] = (float(*)[KP][64])(smraw + 4096);      // [4][32][64]
    const int tid = threadIdx.x;
    const int n  = tid & 63;
    const int kp = tid >> 6;
    const int ng = (b & 3) * 64 + n;
    const int cbase = (b >> 2) * 32;

#pragma unroll
    for (int r = 0; r < 4; r++) {
        int idx = tid + 256 * r;
        int ii = idx >> 5, k = idx & 31;
        a_s[ii][k] = proto[k * C + cbase + ii];
    }
    __syncthreads();

    float acc[KP];
#pragma unroll
    for (int k = 0; k < KP; k++) acc[k] = 0.f;

    const float* wptr = Wc1 + (size_t)(cbase + kp * 8) * HCONF + ng;
    float wv[8];
#pragma unroll
    for (int ii = 0; ii < 8; ii++) wv[ii] = wptr[(size_t)ii * HCONF];
#pragma unroll
    for (int ii = 0; ii < 8; ii++) {
        const float w = wv[ii];
        const float4* av = (const float4*)&a_s[kp * 8 + ii][0];
#pragma unroll
        for (int k4 = 0; k4 < 8; k4++) {
            float4 a4 = av[k4];
            acc[k4 * 4 + 0] = fmaf(a4.x, w, acc[k4 * 4 + 0]);
            acc[k4 * 4 + 1] = fmaf(a4.y, w, acc[k4 * 4 + 1]);
            acc[k4 * 4 + 2] = fmaf(a4.z, w, acc[k4 * 4 + 2]);
            acc[k4 * 4 + 3] = fmaf(a4.w, w, acc[k4 * 4 + 3]);
        }
    }
#pragma unroll
    for (int k = 0; k < KP; k++) red[kp][k][n] = acc[k];
    __syncthreads();
    if (tid < 64) {
#pragma unroll
        for (int k = 0; k < KP; k++) {
            float s = red[0][k][n] + red[1][k][n] + red[2][k][n] + red[3][k][n];
            atomicAdd(&g_hp[k * HCONF + ng], s);
        }
    }
}

__global__ void __launch_bounds__(256) k1_kernel(const float* __restrict__ qd,
                                                 const float* __restrict__ proto,
                                                 const float* __restrict__ Wc1) {
    extern __shared__ char dsm[];
    const int bid = blockIdx.x;
    if (bid < 192)      wmean_role(qd, dsm, bid >> 6, (bid & 63) * 256);
    else if (bid < 448) hq_role(dsm, (bid - 192) * 2);
    else                hp_role(proto, Wc1, dsm, bid - 448);
}

// ================= K2: mlp (blocks 0..127) + conf (128..287) =================
__device__ __forceinline__ void grid_sync_at(unsigned want) {
    __threadfence();
    __syncthreads();
    if (threadIdx.x == 0) {
        atomicAdd(&g_bar, 1u);
        while (*(volatile unsigned*)&g_bar < want) __nanosleep(32);
    }
    __syncthreads();
}

__device__ __forceinline__ void mlp_role(float* __restrict__ refined,
        const float* __restrict__ W1, const float* __restrict__ W2,
        const float* __restrict__ b1, const float* __restrict__ b2, char* smraw) {
    float (*a_s)[KP] = (float(*)[KP])smraw;                         // [64][32] 8 KB
    float (*red)[KP][64] = (float(*)[KP][64])(smraw + 8192);        // [4][32][64] 32 KB
    float (*s_winv)[KP] = (float(*)[KP])(smraw + 8192 + 32768);     // [3][32]

    const int tid = threadIdx.x;
    const int n  = tid & 63;
    const int kp = tid >> 6;
    const int bx = blockIdx.x & 7;
    const int by = blockIdx.x >> 3;

    if (tid < NSTEPS * KP)
        s_winv[tid >> 5][tid & 31] = 1.0f / fmaxf(g_wsum[tid], 1e-6f);

    unsigned want = MLPB;

    for (int step = 0; step < NSTEPS; step++) {
        {
            const int ng = bx * 64 + n;
            const int kbase = by * 64;
            __syncthreads();
#pragma unroll
            for (int r = 0; r < 8; r++) {
                int idx = tid + 256 * r;
                int ii = idx >> 5, k = idx & 31;
                int i = kbase + ii;
                a_s[ii][k] = (i < C)
                    ? __ldcg(&refined[k * C + i])
                    : g_wmean[(size_t)(step * KP + k) * C + (i - C)] * s_winv[step][k];
            }
            __syncthreads();

            float acc[KP];
#pragma unroll
            for (int k = 0; k < KP; k++) acc[k] = 0.f;

            const float* wptr = W1 + (size_t)(kbase + kp * 16) * HREF + ng;
            float wv[16];
#pragma unroll
            for (int ii = 0; ii < 16; ii++) wv[ii] = wptr[(size_t)ii * HREF];
#pragma unroll
            for (int ii = 0; ii < 16; ii++) {
                const float w = wv[ii];
                const float4* av = (const float4*)&a_s[kp * 16 + ii][0];
#pragma unroll
                for (int k4 = 0; k4 < 8; k4++) {
                    float4 a4 = av[k4];
                    acc[k4 * 4 + 0] = fmaf(a4.x, w, acc[k4 * 4 + 0]);
                    acc[k4 * 4 + 1] = fmaf(a4.y, w, acc[k4 * 4 + 1]);
                    acc[k4 * 4 + 2] = fmaf(a4.z, w, acc[k4 * 4 + 2]);
                    acc[k4 * 4 + 3] = fmaf(a4.w, w, acc[k4 * 4 + 3]);
                }
            }
#pragma unroll
            for (int k = 0; k < KP; k++) red[kp][k][n] = acc[k];
            __syncthreads();
            if (tid < 64) {
#pragma unroll
                for (int k = 0; k < KP; k++) {
                    float s = red[0][k][n] + red[1][k][n] + red[2][k][n] + red[3][k][n];
                    atomicAdd(&g_h[(size_t)(step * KP + k) * HREF + ng], s);
                }
            }
        }
        grid_sync_at(want); want += MLPB;

        {
            const int cg = bx * 64 + n;
            const int jbase = by * 32;
#pragma unroll
            for (int r = 0; r < 4; r++) {
                int idx = tid + 256 * r;
                int ii = idx >> 5, k = idx & 31;
                int j = jbase + ii;
                a_s[ii][k] = fmaxf(__ldcg(&g_h[(size_t)(step * KP + k) * HREF + j]) + b1[j], 0.f);
            }
            __syncthreads();

            float acc[KP];
#pragma unroll
            for (int k = 0; k < KP; k++) acc[k] = 0.f;

            const float* wptr = W2 + (size_t)(jbase + kp * 8) * C + cg;
            float wv[8];
#pragma unroll
            for (int ii = 0; ii < 8; ii++) wv[ii] = wptr[(size_t)ii * C];
#pragma unroll
            for (int ii = 0; ii < 8; ii++) {
                const float w = wv[ii];
                const float4* av = (const float4*)&a_s[kp * 8 + ii][0];
#pragma unroll
                for (int k4 = 0; k4 < 8; k4++) {
                    float4 a4 = av[k4];
                    acc[k4 * 4 + 0] = fmaf(a4.x, w, acc[k4 * 4 + 0]);
                    acc[k4 * 4 + 1] = fmaf(a4.y, w, acc[k4 * 4 + 1]);
                    acc[k4 * 4 + 2] = fmaf(a4.z, w, acc[k4 * 4 + 2]);
                    acc[k4 * 4 + 3] = fmaf(a4.w, w, acc[k4 * 4 + 3]);
                }
            }
#pragma unroll
            for (int k = 0; k < KP; k++) red[kp][k][n] = acc[k];
            __syncthreads();
            if (tid < 64) {
                const float b2v = (by == 0) ? b2[cg] : 0.f;
#pragma unroll
                for (int k = 0; k < KP; k++) {
                    float s = red[0][k][n] + red[1][k][n] + red[2][k][n] + red[3][k][n];
                    atomicAdd(&refined[k * C + cg], 0.1f * (s + b2v));
                }
            }
        }
        if (step < NSTEPS - 1) { grid_sync_at(want); want += MLPB; }
    }
}

__device__ __forceinline__ void conf_role(const float* __restrict__ Wc2,
        const float* __restrict__ bc1, const float* __restrict__ bc2,
        float* __restrict__ out, char* smraw, int cb) {
    float (*s_hp)[HCONF] = (float(*)[HCONF])smraw;                  // [32][256] 32 KB
    float (*s_part)[KP] = (float(*)[KP])(smraw + 32768);            // [8][32]
    unsigned* s_last = (unsigned*)(smraw + 32768 + 1024);
    const int tid  = threadIdx.x;
    const int lane = tid & 31;
    const int warp = tid >> 5;

    float* hpflat = &s_hp[0][0];
#pragma unroll
    for (int r = 0; r < 32; r++) hpflat[tid + 256 * r] = g_hp[tid + 256 * r];

    float wc2r[8], bcr[8];
#pragma unroll
    for (int j = 0; j < 8; j++) {
        wc2r[j] = Wc2[lane + 32 * j];
        bcr[j]  = bc1[lane + 32 * j];
    }
    const float bc2v = bc2[0];
    __syncthreads();

    float conf_acc = 0.f;
    const int nwarps = CONFB * 8;
    for (int q = cb * 8 + warp; q < NQ; q += nwarps) {
        float a[8];
#pragma unroll
        for (int j = 0; j < 8; j++) a[j] = g_hq[(size_t)q * HCONF + lane + 32 * j] + bcr[j];
#pragma unroll 4
        for (int k = 0; k < KP; k++) {
            float s = 0.f;
#pragma unroll
            for (int j = 0; j < 8; j++) {
                float t = fmaxf(s_hp[k][lane + 32 * j] + a[j], 0.f);
                s = fmaf(t, wc2r[j], s);
            }
            s += __shfl_xor_sync(0xffffffffu, s, 16);
            s += __shfl_xor_sync(0xffffffffu, s, 8);
            s += __shfl_xor_sync(0xffffffffu, s, 4);
            s += __shfl_xor_sync(0xffffffffu, s, 2);
            s += __shfl_xor_sync(0xffffffffu, s, 1);
            const float sig = 1.0f / (1.0f + __expf(-(s + bc2v)));
            if (k == lane) conf_acc += sig;
        }
    }
    s_part[warp][lane] = conf_acc;
    __syncthreads();
    if (tid < KP) {
        float t = 0.f;
#pragma unroll
        for (int w = 0; w < 8; w++) t += s_part[w][tid];
        atomicAdd(&g_conf[tid], t);
    }
    __threadfence();
    __syncthreads();
    if (tid == 0) *s_last = atomicAdd(&g_cdone, 1u);
    __syncthreads();
    if (*s_last == CONFB - 1) {
        if (tid < KP)
            out[KP * C + tid] = *((volatile float*)&g_conf[tid]) * (1.0f / (float)NQ);
    }
}

#define K2_SMEM 41472
__global__ void __launch_bounds__(256) k2_kernel(float* __restrict__ out,
        const float* __restrict__ W1, const float* __restrict__ W2,
        const float* __restrict__ b1, const float* __restrict__ b2,
        const float* __restrict__ Wc2, const float* __restrict__ bc1,
        const float* __restrict__ bc2) {
    extern __shared__ char dsm[];
    const int bid = blockIdx.x;
    if (bid < MLPB) mlp_role(out, W1, W2, b1, b2, dsm);
    else            conf_role(Wc2, bc1, bc2, out, dsm, bid - MLPB);
}

// ---------------- launch ----------------
extern "C" void kernel_launch(void* const* d_in, const int* in_sizes, int n_in,
                              void* d_out, int out_size) {
    const float* proto = (const float*)d_in[0];
    const float* qf    = (const float*)d_in[1];
    const float* qd    = (const float*)d_in[2];
    const float* W1    = (const float*)d_in[3];
    const float* b1    = (const float*)d_in[4];
    const float* W2    = (const float*)d_in[5];
    const float* b2    = (const float*)d_in[6];
    const float* Wc1   = (const float*)d_in[7];
    const float* bc1   = (const float*)d_in[8];
    const float* Wc2   = (const float*)d_in[9];
    const float* bc2   = (const float*)d_in[10];
    float* out = (float*)d_out;

    static int smem_set = 0;
    if (!smem_set) {
        cudaFuncSetAttribute(k1_kernel, cudaFuncAttributeMaxDynamicSharedMemorySize, K1_SMEM);
        cudaFuncSetAttribute(k2_kernel, cudaFuncAttributeMaxDynamicSharedMemorySize, K2_SMEM);
        smem_set = 1;
    }

    k0_kernel<<<4352, 256>>>(proto, qf, Wc1, out);
    k1_kernel<<<512, 256, K1_SMEM>>>(qd, proto, Wc1);
    k2_kernel<<<MLPB + CONFB, 256, K2_SMEM>>>(out, W1, W2, b1, b2, Wc2, bc1, bc2);
}